// round 4
// baseline (speedup 1.0000x reference)
#include <cuda_runtime.h>

// Problem constants
#define B_   64
#define C_   256
#define HW_  4096
#define EMB_ 512
#define BT   4                 // batches per chain warp-task
#define NCB  1024              // chain blocks (must all be wave-1 resident)
#define NTASK 4096             // C_ * (B_/BT) tasks per stage
#define GRID (B_ * C_)         // 16384 streaming blocks

// Scratch + sync state (allocation-free rule: __device__ globals, zero-init)
__device__ float g_t1[B_ * C_];
__device__ float g_t2[B_ * C_];
__device__ float g_av[B_ * C_];
__device__ int   g_s1, g_s2, g_s3, g_done;

// ---------------------------------------------------------------------------
// One chain task: out[(b0+j)*C + r] = dot(W[r], in[b0+j], LEN) + bias[r], j<BT
// ---------------------------------------------------------------------------
template <int LEN>
__device__ __forceinline__ void stage_task(
    const float* __restrict__ W, const float* __restrict__ invec,
    const float* __restrict__ bias, float* __restrict__ out,
    int task, int lane)
{
    const int r  = task & (C_ - 1);
    const int b0 = (task >> 8) * BT;
    const float4* __restrict__ wrow = reinterpret_cast<const float4*>(W + (size_t)r * LEN);
    const float4* __restrict__ xin  = reinterpret_cast<const float4*>(invec + (size_t)b0 * LEN);

    float acc[BT];
    #pragma unroll
    for (int j = 0; j < BT; j++) acc[j] = 0.f;

    #pragma unroll
    for (int k = lane; k < LEN / 4; k += 32) {
        const float4 a = wrow[k];
        #pragma unroll
        for (int j = 0; j < BT; j++) {
            const float4 c = xin[(size_t)j * (LEN / 4) + k];
            acc[j] += a.x * c.x + a.y * c.y + a.z * c.z + a.w * c.w;
        }
    }
    #pragma unroll
    for (int j = 0; j < BT; j++) {
        #pragma unroll
        for (int o = 16; o > 0; o >>= 1)
            acc[j] += __shfl_down_sync(0xffffffffu, acc[j], o);
    }
    if (lane == 0) {
        const float bs = bias[r];
        #pragma unroll
        for (int j = 0; j < BT; j++)
            out[(size_t)(b0 + j) * C_ + r] = acc[j] + bs;
    }
}

// Release-arrive + acquire-wait soft barrier among the NCB chain blocks.
__device__ __forceinline__ void soft_barrier(int* cnt)
{
    __syncthreads();
    if (threadIdx.x == 0) {
        __threadfence();                       // release prior writes
        atomicAdd(cnt, 1);
        volatile int* vc = (volatile int*)cnt;
        while (*vc < NCB) __nanosleep(64);
        __threadfence();                       // acquire
    }
    __syncthreads();
}

// ---------------------------------------------------------------------------
// Fused kernel: chain (blocks 0..NCB-1) overlapped with x-stream (all blocks).
// ---------------------------------------------------------------------------
__global__ void __launch_bounds__(256, 8) fused_kernel(
    const float* __restrict__ x,
    const float* __restrict__ cond_emb,
    const float* __restrict__ in_proj_w,
    const float* __restrict__ in_proj_b,
    const float* __restrict__ out_w,
    const float* __restrict__ out_b,
    const float* __restrict__ kv_w,
    const float* __restrict__ kv_b,
    float* __restrict__ y)
{
    const int bid  = blockIdx.x;
    const int tid  = threadIdx.x;
    const int lane = tid & 31;
    __shared__ float s_av;

    // ---- chain (first NCB blocks; all wave-1 resident by placement order) ----
    if (bid < NCB) {
        const int gw = bid * 8 + (tid >> 5);       // 0 .. 8191
        if (gw < NTASK)
            stage_task<EMB_>(kv_w + (size_t)C_ * EMB_, cond_emb, kv_b + C_, g_t1, gw, lane);
        soft_barrier(&g_s1);
        if (gw < NTASK)
            stage_task<C_>(in_proj_w + (size_t)2 * C_ * C_, g_t1, in_proj_b + 2 * C_, g_t2, gw, lane);
        soft_barrier(&g_s2);
        if (gw < NTASK)
            stage_task<C_>(out_w, g_t2, out_b, g_av, gw, lane);
        __syncthreads();
        if (tid == 0) { __threadfence(); atomicAdd(&g_s3, 1); }
    }

    // ---- streaming: y[bc, :] = x[bc, :] + av[bc]  (4096 floats per block) ----
    const float4* __restrict__ xi = reinterpret_cast<const float4*>(x) + (size_t)bid * (HW_ / 4);
    float4* __restrict__       yo = reinterpret_cast<float4*>(y)       + (size_t)bid * (HW_ / 4);

    // Issue loads before the flag wait so they overlap the chain.
    float4 v0 = xi[tid];
    float4 v1 = xi[tid + 256];
    float4 v2 = xi[tid + 512];
    float4 v3 = xi[tid + 768];

    if (tid == 0) {
        volatile int* vs = (volatile int*)&g_s3;
        while (*vs < NCB) __nanosleep(128);
        __threadfence();                       // acquire g_av
        s_av = g_av[bid];
    }
    __syncthreads();
    const float a = s_av;

    v0.x += a; v0.y += a; v0.z += a; v0.w += a;
    v1.x += a; v1.y += a; v1.z += a; v1.w += a;
    v2.x += a; v2.y += a; v2.z += a; v2.w += a;
    v3.x += a; v3.y += a; v3.z += a; v3.w += a;
    yo[tid]       = v0;
    yo[tid + 256] = v1;
    yo[tid + 512] = v2;
    yo[tid + 768] = v3;

    // ---- epilogue: last block resets sync state for the next graph replay ----
    __syncthreads();
    if (tid == 0) {
        __threadfence();
        const int ticket = atomicAdd(&g_done, 1);
        if (ticket == GRID - 1) {
            g_s1 = 0; g_s2 = 0; g_s3 = 0; g_done = 0;
            __threadfence();
        }
    }
}

extern "C" void kernel_launch(void* const* d_in, const int* in_sizes, int n_in,
                              void* d_out, int out_size)
{
    // metadata order: x, cond_emb, ln_gamma, ln_beta, in_proj_w, in_proj_b,
    //                 out_w, out_b, kv_w, kv_b
    const float* x         = (const float*)d_in[0];
    const float* cond_emb  = (const float*)d_in[1];
    // ln_gamma/ln_beta provably do not affect the output: softmax over the
    // size-1 KV axis is exactly 1, so q (and thus x_ln) cancels.
    const float* in_proj_w = (const float*)d_in[4];
    const float* in_proj_b = (const float*)d_in[5];
    const float* out_w     = (const float*)d_in[6];
    const float* out_b     = (const float*)d_in[7];
    const float* kv_w      = (const float*)d_in[8];
    const float* kv_b      = (const float*)d_in[9];
    float* y = (float*)d_out;

    fused_kernel<<<GRID, 256>>>(x, cond_emb, in_proj_w, in_proj_b,
                                out_w, out_b, kv_w, kv_b, y);
}

// round 5
// speedup vs baseline: 1.0184x; 1.0184x over previous
#include <cuda_runtime.h>

// Problem constants
#define B_   64
#define C_   256
#define HW_  4096
#define EMB_ 512
#define BT   8                 // batches per chain warp-task
#define CHB  256               // chain grid blocks (must be <= 1-wave residency)
#define NTASK 2048             // C_ * (B_/BT) tasks per stage

// Scratch + sync state (allocation-free rule: __device__ globals, zero-init)
__device__ float g_t1[B_ * C_];
__device__ float g_t2[B_ * C_];
__device__ float g_av[B_ * C_];
__device__ int   g_s1, g_s2, g_done;

// ---------------------------------------------------------------------------
// One chain task: out[(b0+j)*C + r] = dot(W[r], in[b0+j], LEN) + bias[r], j<BT
// Weight row read once per 8 batches; inputs L1-resident.
// ---------------------------------------------------------------------------
template <int LEN>
__device__ __forceinline__ void stage_task(
    const float* __restrict__ W, const float* __restrict__ invec,
    const float* __restrict__ bias, float* __restrict__ out,
    int task, int lane)
{
    const int r  = task & (C_ - 1);
    const int b0 = (task >> 8) * BT;
    const float4* __restrict__ wrow = reinterpret_cast<const float4*>(W + (size_t)r * LEN);
    const float4* __restrict__ xin  = reinterpret_cast<const float4*>(invec + (size_t)b0 * LEN);

    float acc[BT];
    #pragma unroll
    for (int j = 0; j < BT; j++) acc[j] = 0.f;

    #pragma unroll
    for (int k = lane; k < LEN / 4; k += 32) {
        const float4 a = wrow[k];
        #pragma unroll
        for (int j = 0; j < BT; j++) {
            const float4 c = xin[(size_t)j * (LEN / 4) + k];
            acc[j] += a.x * c.x + a.y * c.y + a.z * c.z + a.w * c.w;
        }
    }
    #pragma unroll
    for (int j = 0; j < BT; j++) {
        #pragma unroll
        for (int o = 16; o > 0; o >>= 1)
            acc[j] += __shfl_down_sync(0xffffffffu, acc[j], o);
    }
    if (lane == 0) {
        const float bs = bias[r];
        #pragma unroll
        for (int j = 0; j < BT; j++)
            out[(size_t)(b0 + j) * C_ + r] = acc[j] + bs;
    }
}

// Release + acquire soft barrier among the CHB chain blocks (all co-resident).
__device__ __forceinline__ void soft_barrier(int* cnt)
{
    __syncthreads();
    if (threadIdx.x == 0) {
        __threadfence();                       // release prior global writes
        atomicAdd(cnt, 1);
        volatile int* vc = (volatile int*)cnt;
        while (*vc < CHB) __nanosleep(32);
        __threadfence();                       // acquire
    }
    __syncthreads();
}

// ---------------------------------------------------------------------------
// Chain kernel: all three tiny-GEMM stages in one launch.
// grid = CHB (=256) blocks, guaranteed single-wave resident (148 SMs, 8 blk/SM).
// ---------------------------------------------------------------------------
__global__ void __launch_bounds__(256, 8) chain_kernel(
    const float* __restrict__ cond_emb,
    const float* __restrict__ in_proj_w,
    const float* __restrict__ in_proj_b,
    const float* __restrict__ out_w,
    const float* __restrict__ out_b,
    const float* __restrict__ kv_w,
    const float* __restrict__ kv_b)
{
    const int lane = threadIdx.x & 31;
    const int gw   = blockIdx.x * 8 + (threadIdx.x >> 5);   // 0 .. 2047 == NTASK-1

    // Stage 1: t1[b] = kv_w[C:2C] @ ce[b] + kv_b[C:]
    stage_task<EMB_>(kv_w + (size_t)C_ * EMB_, cond_emb, kv_b + C_, g_t1, gw, lane);
    soft_barrier(&g_s1);
    // Stage 2: t2[b] = wv @ t1[b] + bv
    stage_task<C_>(in_proj_w + (size_t)2 * C_ * C_, g_t1, in_proj_b + 2 * C_, g_t2, gw, lane);
    soft_barrier(&g_s2);
    // Stage 3: av[b] = out_w @ t2[b] + out_b
    stage_task<C_>(out_w, g_t2, out_b, g_av, gw, lane);

    // Reset sync counters for the next graph replay (ticketed last block).
    __syncthreads();
    if (threadIdx.x == 0) {
        __threadfence();
        if (atomicAdd(&g_done, 1) == CHB - 1) {
            g_s1 = 0; g_s2 = 0; g_done = 0;
            __threadfence();
        }
    }
}

// ---------------------------------------------------------------------------
// Stream kernel: y[bc, :] = x[bc, :] + av[bc]. Identical to the measured-best
// R1 form (74.3us, 81.8% DRAM). Plain float4 loads/stores.
// ---------------------------------------------------------------------------
__global__ void __launch_bounds__(256) broadcast_add_kernel(
    const float* __restrict__ x,
    float* __restrict__ y)
{
    const int bc = blockIdx.x;                 // 0 .. B*C-1
    const float a = g_av[bc];

    const float4* __restrict__ xi = reinterpret_cast<const float4*>(x) + (size_t)bc * (HW_ / 4);
    float4* __restrict__       yo = reinterpret_cast<float4*>(y)       + (size_t)bc * (HW_ / 4);

    #pragma unroll
    for (int t = 0; t < 4; t++) {
        const int i = threadIdx.x + t * 256;
        float4 v = xi[i];
        v.x += a; v.y += a; v.z += a; v.w += a;
        yo[i] = v;
    }
}

extern "C" void kernel_launch(void* const* d_in, const int* in_sizes, int n_in,
                              void* d_out, int out_size)
{
    // metadata order: x, cond_emb, ln_gamma, ln_beta, in_proj_w, in_proj_b,
    //                 out_w, out_b, kv_w, kv_b
    const float* x         = (const float*)d_in[0];
    const float* cond_emb  = (const float*)d_in[1];
    // ln_gamma/ln_beta provably do not affect the output: softmax over the
    // size-1 KV axis is exactly 1, so q (and thus x_ln) cancels.
    const float* in_proj_w = (const float*)d_in[4];
    const float* in_proj_b = (const float*)d_in[5];
    const float* out_w     = (const float*)d_in[6];
    const float* out_b     = (const float*)d_in[7];
    const float* kv_w      = (const float*)d_in[8];
    const float* kv_b      = (const float*)d_in[9];
    float* y = (float*)d_out;

    chain_kernel<<<CHB, 256>>>(cond_emb, in_proj_w, in_proj_b,
                               out_w, out_b, kv_w, kv_b);
    broadcast_add_kernel<<<B_ * C_, 256>>>(x, y);
}

// round 7
// speedup vs baseline: 1.1180x; 1.0978x over previous
#include <cuda_runtime.h>

// Problem constants
#define B_   64
#define C_   256
#define HW_  4096
#define EMB_ 512
#define BT   2                              // batches per warp-task
#define NTASK (C_ * (B_ / BT))              // 8192 tasks per stage
#define STG_BLOCKS (NTASK / 8)              // 1024 blocks x 8 warps

// Scratch (allocation-free rule: __device__ globals)
__device__ float g_t1[B_ * C_];
__device__ float g_t2[B_ * C_];

// ---------------------------------------------------------------------------
// Stage: out[(b0+j)*C + r] = dot(W[r], in[b0+j], LEN) + bias[r], j < BT.
// One warp per (row, batch-pair). float4 loads, ~30 regs, no spills.
// ---------------------------------------------------------------------------
template <int LEN>
__global__ void __launch_bounds__(256) stage_kernel(
    const float* __restrict__ W,      // (C_, LEN) row-major (pre-offset)
    const float* __restrict__ invec,  // (B_, LEN)
    const float* __restrict__ bias,   // (C_,) pre-offset
    float* __restrict__ out)          // (B_, C_)
{
    const int lane = threadIdx.x & 31;
    const int gw   = blockIdx.x * 8 + (threadIdx.x >> 5);   // 0 .. NTASK-1
    const int r    = gw & (C_ - 1);
    const int b0   = (gw >> 8) * BT;

    const float4* __restrict__ wrow = reinterpret_cast<const float4*>(W + (size_t)r * LEN);
    const float4* __restrict__ xin  = reinterpret_cast<const float4*>(invec + (size_t)b0 * LEN);

    float acc0 = 0.f, acc1 = 0.f;
    #pragma unroll
    for (int k = lane; k < LEN / 4; k += 32) {
        const float4 a  = wrow[k];
        const float4 c0 = xin[k];
        const float4 c1 = xin[(LEN / 4) + k];
        acc0 += a.x * c0.x + a.y * c0.y + a.z * c0.z + a.w * c0.w;
        acc1 += a.x * c1.x + a.y * c1.y + a.z * c1.z + a.w * c1.w;
    }
    #pragma unroll
    for (int o = 16; o > 0; o >>= 1) {
        acc0 += __shfl_down_sync(0xffffffffu, acc0, o);
        acc1 += __shfl_down_sync(0xffffffffu, acc1, o);
    }
    if (lane == 0) {
        const float bs = bias[r];
        out[(size_t)b0 * C_ + r]       = acc0 + bs;
        out[(size_t)(b0 + 1) * C_ + r] = acc1 + bs;
    }
}

// ---------------------------------------------------------------------------
// Stream kernel with inline stage 3:
//   a      = dot(out_w[c,:], t2[b,:]) + out_b[c]     (one mul/thread + reduce)
//   y[bc,:] = x[bc,:] + a
// The dot's loads are L2-resident (out_w: 256KB, t2: 64KB) and the compute
// hides under the 4 in-flight x float4 loads issued first.
// ---------------------------------------------------------------------------
__global__ void __launch_bounds__(256) broadcast_add_kernel(
    const float* __restrict__ x,
    const float* __restrict__ out_w,   // (C_, C_)
    const float* __restrict__ out_b,   // (C_,)
    float* __restrict__ y)
{
    const int bc   = blockIdx.x;                 // 0 .. B*C-1
    const int b    = bc >> 8;
    const int c    = bc & (C_ - 1);
    const int tid  = threadIdx.x;
    const int lane = tid & 31;
    const int warp = tid >> 5;

    const float4* __restrict__ xi = reinterpret_cast<const float4*>(x) + (size_t)bc * (HW_ / 4);
    float4* __restrict__       yo = reinterpret_cast<float4*>(y)       + (size_t)bc * (HW_ / 4);

    // Issue the streaming loads first (they dominate; dot hides beneath them).
    float4 v0 = xi[tid];
    float4 v1 = xi[tid + 256];
    float4 v2 = xi[tid + 512];
    float4 v3 = xi[tid + 768];

    // Inline stage 3: 256-dot across the block.
    float p = out_w[(size_t)c * C_ + tid] * g_t2[(size_t)b * C_ + tid];
    #pragma unroll
    for (int o = 16; o > 0; o >>= 1)
        p += __shfl_down_sync(0xffffffffu, p, o);

    __shared__ float s_part[8];
    __shared__ float s_a;
    if (lane == 0) s_part[warp] = p;
    __syncthreads();
    if (tid < 8) {
        float q = s_part[tid];
        q += __shfl_down_sync(0x000000ffu, q, 4);
        q += __shfl_down_sync(0x000000ffu, q, 2);
        q += __shfl_down_sync(0x000000ffu, q, 1);
        if (tid == 0) s_a = q + out_b[c];
    }
    __syncthreads();
    const float a = s_a;

    v0.x += a; v0.y += a; v0.z += a; v0.w += a;
    v1.x += a; v1.y += a; v1.z += a; v1.w += a;
    v2.x += a; v2.y += a; v2.z += a; v2.w += a;
    v3.x += a; v3.y += a; v3.z += a; v3.w += a;
    yo[tid]       = v0;
    yo[tid + 256] = v1;
    yo[tid + 512] = v2;
    yo[tid + 768] = v3;
}

extern "C" void kernel_launch(void* const* d_in, const int* in_sizes, int n_in,
                              void* d_out, int out_size)
{
    // metadata order: x, cond_emb, ln_gamma, ln_beta, in_proj_w, in_proj_b,
    //                 out_w, out_b, kv_w, kv_b
    const float* x         = (const float*)d_in[0];
    const float* cond_emb  = (const float*)d_in[1];
    // ln_gamma/ln_beta provably do not affect the output: softmax over the
    // size-1 KV axis is exactly 1, so q (and thus x_ln) cancels.
    const float* in_proj_w = (const float*)d_in[4];
    const float* in_proj_b = (const float*)d_in[5];
    const float* out_w     = (const float*)d_in[6];
    const float* out_b     = (const float*)d_in[7];
    const float* kv_w      = (const float*)d_in[8];
    const float* kv_b      = (const float*)d_in[9];
    float* y = (float*)d_out;

    float *t1, *t2;
    cudaGetSymbolAddress((void**)&t1, g_t1);
    cudaGetSymbolAddress((void**)&t2, g_t2);

    // Stage 1: t1[b] = kv_w[C:2C] @ ce[b] + kv_b[C:]
    stage_kernel<EMB_><<<STG_BLOCKS, 256>>>(kv_w + (size_t)C_ * EMB_, cond_emb,
                                            kv_b + C_, t1);
    // Stage 2: t2[b] = wv @ t1[b] + bv
    stage_kernel<C_><<<STG_BLOCKS, 256>>>(in_proj_w + (size_t)2 * C_ * C_, t1,
                                          in_proj_b + 2 * C_, t2);
    // Stage 3 fused into the stream kernel.
    broadcast_add_kernel<<<B_ * C_, 256>>>(x, out_w, out_b, y);
}